// round 1
// baseline (speedup 1.0000x reference)
#include <cuda_runtime.h>
#include <math.h>

#define D_MODEL 1024
#define NHEAD   16
#define DK      64
#define BATCH   2
#define SEQ     2048
#define MROWS   (BATCH * SEQ)          // 4096
#define OUT_ELEMS ((size_t)MROWS * D_MODEL)             // 4,194,304
#define ATTN_ELEMS ((size_t)BATCH * NHEAD * SEQ * SEQ)  // 134,217,728

// Scratch (no cudaMalloc allowed)
__device__ float g_Q[MROWS * D_MODEL];
__device__ float g_K[MROWS * D_MODEL];
__device__ float g_V[MROWS * D_MODEL];
__device__ float g_ctx[MROWS * D_MODEL];

// ---------------------------------------------------------------------------
// Generic tiled fp32 GEMM + bias:  Y[M,N] = X[M,K] @ W[K,N] + b[N]
// M=4096, N=1024, K=1024. Tile 64x64, BK=16, 256 threads, 4x4 per thread.
// ---------------------------------------------------------------------------
__global__ __launch_bounds__(256) void gemm_bias_kernel(
    const float* __restrict__ X, const float* __restrict__ W,
    const float* __restrict__ bias, float* __restrict__ Y)
{
    const int N = D_MODEL, K = D_MODEL;
    __shared__ float As[16][64];   // [k][m]
    __shared__ float Bs[16][64];   // [k][n]

    int tid = threadIdx.x;
    int tx = tid & 15, ty = tid >> 4;
    int rowBase = blockIdx.y * 64;
    int colBase = blockIdx.x * 64;

    float acc[4][4] = {};

    for (int k0 = 0; k0 < K; k0 += 16) {
        // A tile 64x16 -> As[k][m] (transposed store)
        {
            int e = tid * 4;
            int m = e >> 4;
            int k = e & 15;
            float4 v = *reinterpret_cast<const float4*>(&X[(size_t)(rowBase + m) * K + k0 + k]);
            As[k + 0][m] = v.x; As[k + 1][m] = v.y; As[k + 2][m] = v.z; As[k + 3][m] = v.w;
        }
        // B tile 16x64 -> Bs[k][n]
        {
            int e = tid * 4;
            int k = e >> 6;
            int n = e & 63;
            float4 v = *reinterpret_cast<const float4*>(&W[(size_t)(k0 + k) * N + colBase + n]);
            *reinterpret_cast<float4*>(&Bs[k][n]) = v;
        }
        __syncthreads();
        #pragma unroll
        for (int k = 0; k < 16; k++) {
            float a[4], b[4];
            #pragma unroll
            for (int i = 0; i < 4; i++) a[i] = As[k][ty * 4 + i];
            #pragma unroll
            for (int j = 0; j < 4; j++) b[j] = Bs[k][tx * 4 + j];
            #pragma unroll
            for (int i = 0; i < 4; i++)
                #pragma unroll
                for (int j = 0; j < 4; j++)
                    acc[i][j] = fmaf(a[i], b[j], acc[i][j]);
        }
        __syncthreads();
    }

    #pragma unroll
    for (int i = 0; i < 4; i++) {
        int row = rowBase + ty * 4 + i;
        #pragma unroll
        for (int j = 0; j < 4; j++) {
            int col = colBase + tx * 4 + j;
            Y[(size_t)row * N + col] = acc[i][j] + bias[col];
        }
    }
}

// ---------------------------------------------------------------------------
// Scores: attn_raw[b,h,q,s] = (Q[b,q,h*64:..] . K[b,s,h*64:..]) / 8
// Block: one (b,h, q-tile of 64). Loops over 32 key tiles of 64.
// ---------------------------------------------------------------------------
__global__ __launch_bounds__(256) void scores_kernel(
    const float* __restrict__ Q, const float* __restrict__ Kmat,
    float* __restrict__ attn)
{
    __shared__ float Qs[64][65];
    __shared__ float Ks[64][65];

    int qTile = blockIdx.x;          // 0..31
    int bh    = blockIdx.y;          // 0..31
    int b = bh >> 4, h = bh & 15;
    int qBase = qTile * 64;

    int tid = threadIdx.x;
    int tx = tid & 15, ty = tid >> 4;

    // Load Q tile 64x64
    #pragma unroll
    for (int i = 0; i < 4; i++) {
        int e = (tid + i * 256) * 4;
        int r = e >> 6;
        int c = e & 63;
        float4 v = *reinterpret_cast<const float4*>(
            &Q[((size_t)(b * SEQ + qBase + r)) * D_MODEL + h * DK + c]);
        Qs[r][c + 0] = v.x; Qs[r][c + 1] = v.y; Qs[r][c + 2] = v.z; Qs[r][c + 3] = v.w;
    }
    __syncthreads();

    const float scale = 0.125f;  // 1/sqrt(64)

    for (int kt = 0; kt < SEQ / 64; kt++) {
        int kBase = kt * 64;
        #pragma unroll
        for (int i = 0; i < 4; i++) {
            int e = (tid + i * 256) * 4;
            int r = e >> 6;
            int c = e & 63;
            float4 v = *reinterpret_cast<const float4*>(
                &Kmat[((size_t)(b * SEQ + kBase + r)) * D_MODEL + h * DK + c]);
            Ks[r][c + 0] = v.x; Ks[r][c + 1] = v.y; Ks[r][c + 2] = v.z; Ks[r][c + 3] = v.w;
        }
        __syncthreads();

        float acc[4][4] = {};
        #pragma unroll
        for (int d = 0; d < 64; d++) {
            float a[4], c4[4];
            #pragma unroll
            for (int i = 0; i < 4; i++) a[i] = Qs[ty * 4 + i][d];
            #pragma unroll
            for (int j = 0; j < 4; j++) c4[j] = Ks[tx * 4 + j][d];
            #pragma unroll
            for (int i = 0; i < 4; i++)
                #pragma unroll
                for (int j = 0; j < 4; j++)
                    acc[i][j] = fmaf(a[i], c4[j], acc[i][j]);
        }

        #pragma unroll
        for (int i = 0; i < 4; i++) {
            int q = qBase + ty * 4 + i;
            size_t rowOff = ((size_t)bh * SEQ + q) * SEQ;
            #pragma unroll
            for (int j = 0; j < 4; j++) {
                attn[rowOff + kBase + tx * 4 + j] = acc[i][j] * scale;
            }
        }
        __syncthreads();
    }
}

// ---------------------------------------------------------------------------
// In-place row softmax over attn rows of length 2048. One block per row.
// ---------------------------------------------------------------------------
__global__ __launch_bounds__(256) void softmax_kernel(float* __restrict__ attn)
{
    size_t row = blockIdx.x;
    float* p = attn + row * SEQ;
    int tid = threadIdx.x;
    int lane = tid & 31, warp = tid >> 5;

    __shared__ float sred[8];

    float v[8];
    float mx = -INFINITY;
    #pragma unroll
    for (int i = 0; i < 8; i++) {
        v[i] = p[tid + i * 256];
        mx = fmaxf(mx, v[i]);
    }
    #pragma unroll
    for (int o = 16; o > 0; o >>= 1) mx = fmaxf(mx, __shfl_xor_sync(0xFFFFFFFFu, mx, o));
    if (lane == 0) sred[warp] = mx;
    __syncthreads();
    if (tid < 32) {
        float m = (tid < 8) ? sred[tid] : -INFINITY;
        #pragma unroll
        for (int o = 4; o > 0; o >>= 1) m = fmaxf(m, __shfl_xor_sync(0xFFFFFFFFu, m, o));
        if (tid == 0) sred[0] = m;
    }
    __syncthreads();
    mx = sred[0];
    __syncthreads();

    float sum = 0.0f;
    #pragma unroll
    for (int i = 0; i < 8; i++) {
        v[i] = __expf(v[i] - mx);
        sum += v[i];
    }
    #pragma unroll
    for (int o = 16; o > 0; o >>= 1) sum += __shfl_xor_sync(0xFFFFFFFFu, sum, o);
    if (lane == 0) sred[warp] = sum;
    __syncthreads();
    if (tid < 32) {
        float s = (tid < 8) ? sred[tid] : 0.0f;
        #pragma unroll
        for (int o = 4; o > 0; o >>= 1) s += __shfl_xor_sync(0xFFFFFFFFu, s, o);
        if (tid == 0) sred[0] = s;
    }
    __syncthreads();
    float inv = 1.0f / sred[0];

    #pragma unroll
    for (int i = 0; i < 8; i++) p[tid + i * 256] = v[i] * inv;
}

// ---------------------------------------------------------------------------
// ctx[b,q,h*64+n] = sum_s attn[b,h,q,s] * V[b,s,h*64+n]
// Block: one (b,h, q-tile 64). Tile 64x64 output, BK=16 over s.
// ---------------------------------------------------------------------------
__global__ __launch_bounds__(256) void ctx_kernel(
    const float* __restrict__ attn, const float* __restrict__ V,
    float* __restrict__ ctx)
{
    __shared__ float As[16][64];   // [s][q]
    __shared__ float Bs[16][64];   // [s][n]

    int qTile = blockIdx.x;
    int bh    = blockIdx.y;
    int b = bh >> 4, h = bh & 15;
    int qBase = qTile * 64;

    int tid = threadIdx.x;
    int tx = tid & 15, ty = tid >> 4;

    float acc[4][4] = {};

    for (int k0 = 0; k0 < SEQ; k0 += 16) {
        {
            int e = tid * 4;
            int m = e >> 4;      // q within tile
            int k = e & 15;      // s within chunk
            float4 v = *reinterpret_cast<const float4*>(
                &attn[((size_t)bh * SEQ + qBase + m) * SEQ + k0 + k]);
            As[k + 0][m] = v.x; As[k + 1][m] = v.y; As[k + 2][m] = v.z; As[k + 3][m] = v.w;
        }
        {
            int e = tid * 4;
            int k = e >> 6;
            int n = e & 63;
            float4 v = *reinterpret_cast<const float4*>(
                &V[((size_t)(b * SEQ + k0 + k)) * D_MODEL + h * DK + n]);
            *reinterpret_cast<float4*>(&Bs[k][n]) = v;
        }
        __syncthreads();
        #pragma unroll
        for (int k = 0; k < 16; k++) {
            float a[4], c4[4];
            #pragma unroll
            for (int i = 0; i < 4; i++) a[i] = As[k][ty * 4 + i];
            #pragma unroll
            for (int j = 0; j < 4; j++) c4[j] = Bs[k][tx * 4 + j];
            #pragma unroll
            for (int i = 0; i < 4; i++)
                #pragma unroll
                for (int j = 0; j < 4; j++)
                    acc[i][j] = fmaf(a[i], c4[j], acc[i][j]);
        }
        __syncthreads();
    }

    #pragma unroll
    for (int i = 0; i < 4; i++) {
        int q = qBase + ty * 4 + i;
        #pragma unroll
        for (int j = 0; j < 4; j++) {
            ctx[((size_t)(b * SEQ + q)) * D_MODEL + h * DK + tx * 4 + j] = acc[i][j];
        }
    }
}

// ---------------------------------------------------------------------------
extern "C" void kernel_launch(void* const* d_in, const int* in_sizes, int n_in,
                              void* d_out, int out_size)
{
    const float* query = (const float*)d_in[0];
    const float* key   = (const float*)d_in[1];
    const float* value = (const float*)d_in[2];
    const float* Wq = (const float*)d_in[3];
    const float* bq = (const float*)d_in[4];
    const float* Wk = (const float*)d_in[5];
    const float* bk = (const float*)d_in[6];
    const float* Wv = (const float*)d_in[7];
    const float* bv = (const float*)d_in[8];
    const float* Wo = (const float*)d_in[9];
    const float* bo = (const float*)d_in[10];

    float* out  = (float*)d_out;
    float* attn = (float*)d_out + OUT_ELEMS;

    float* Qp; cudaGetSymbolAddress((void**)&Qp, g_Q);
    float* Kp; cudaGetSymbolAddress((void**)&Kp, g_K);
    float* Vp; cudaGetSymbolAddress((void**)&Vp, g_V);
    float* Cp; cudaGetSymbolAddress((void**)&Cp, g_ctx);

    dim3 gGemm(D_MODEL / 64, MROWS / 64);   // (16, 64)
    dim3 gAttn(SEQ / 64, BATCH * NHEAD);    // (32, 32)

    gemm_bias_kernel<<<gGemm, 256>>>(query, Wq, bq, Qp);
    gemm_bias_kernel<<<gGemm, 256>>>(key,   Wk, bk, Kp);
    gemm_bias_kernel<<<gGemm, 256>>>(value, Wv, bv, Vp);

    scores_kernel<<<gAttn, 256>>>(Qp, Kp, attn);
    softmax_kernel<<<BATCH * NHEAD * SEQ, 256>>>(attn);
    ctx_kernel<<<gAttn, 256>>>(attn, Vp, Cp);

    gemm_bias_kernel<<<gGemm, 256>>>(Cp, Wo, bo, out);
}

// round 2
// speedup vs baseline: 1.7937x; 1.7937x over previous
#include <cuda_runtime.h>
#include <math.h>

#define D_MODEL 1024
#define NHEAD   16
#define DK      64
#define BATCH   2
#define SEQ     2048
#define MROWS   (BATCH * SEQ)
#define OUT_ELEMS ((size_t)MROWS * D_MODEL)

#define BM 128
#define BN 64
#define BK 16
#define ASTR (BM + 4)   // 132
#define BSTR (BN + 4)   // 68

// Scratch (no cudaMalloc allowed)
__device__ float g_Q[MROWS * D_MODEL];
__device__ float g_K[MROWS * D_MODEL];
__device__ float g_V[MROWS * D_MODEL];
__device__ float g_ctx[MROWS * D_MODEL];

// ---------------------------------------------------------------------------
__device__ __forceinline__ unsigned f2tf(float f) {
    unsigned u;
    asm("cvt.rna.tf32.f32 %0, %1;" : "=r"(u) : "f"(f));
    return u;
}

__device__ __forceinline__ void mma_tf32(float* c, const unsigned* a, const unsigned* b) {
    asm volatile(
        "mma.sync.aligned.m16n8k8.row.col.f32.tf32.tf32.f32 "
        "{%0,%1,%2,%3},{%4,%5,%6,%7},{%8,%9},{%0,%1,%2,%3};"
        : "+f"(c[0]), "+f"(c[1]), "+f"(c[2]), "+f"(c[3])
        : "r"(a[0]), "r"(a[1]), "r"(a[2]), "r"(a[3]), "r"(b[0]), "r"(b[1]));
}

// A tile loader: element (m,k) at base + m*strideM + k (k contiguous).
// BM=128 x BK=16 = 2048 floats, 256 threads x 2 float4.
__device__ __forceinline__ void load_A_kcontig(
    const float* __restrict__ base, size_t strideM,
    unsigned (*Ash)[ASTR], unsigned (*Asl)[ASTR], int tid)
{
    #pragma unroll
    for (int i = 0; i < 2; i++) {
        int e = tid + i * 256;          // 0..511
        int m = e >> 2;                 // 0..127
        int k = (e & 3) * 4;
        float4 v = *reinterpret_cast<const float4*>(base + (size_t)m * strideM + k);
        float f[4] = {v.x, v.y, v.z, v.w};
        #pragma unroll
        for (int j = 0; j < 4; j++) {
            unsigned h = f2tf(f[j]);
            Ash[k + j][m] = h;
            Asl[k + j][m] = f2tf(f[j] - __uint_as_float(h));
        }
    }
}

// B tile loader, k-contiguous source: element (k,n) at base + n*strideN + k.
// (scores: B = K matrix, n = s row, k = d contiguous). 64x16 = 256 float4.
__device__ __forceinline__ void load_B_kcontig(
    const float* __restrict__ base, size_t strideN,
    unsigned (*Bsh)[BSTR], unsigned (*Bsl)[BSTR], int tid)
{
    int n = tid >> 2;                   // 0..63
    int k = (tid & 3) * 4;
    float4 v = *reinterpret_cast<const float4*>(base + (size_t)n * strideN + k);
    float f[4] = {v.x, v.y, v.z, v.w};
    #pragma unroll
    for (int j = 0; j < 4; j++) {
        unsigned h = f2tf(f[j]);
        Bsh[k + j][n] = h;
        Bsl[k + j][n] = f2tf(f[j] - __uint_as_float(h));
    }
}

// B tile loader, n-contiguous source: element (k,n) at base + k*strideK + n.
// (weights W[k][n], V[s][d]). 16x64 = 256 float4.
__device__ __forceinline__ void load_B_ncontig(
    const float* __restrict__ base, size_t strideK,
    unsigned (*Bsh)[BSTR], unsigned (*Bsl)[BSTR], int tid)
{
    int k = tid >> 4;                   // 0..15
    int n = (tid & 15) * 4;
    float4 v = *reinterpret_cast<const float4*>(base + (size_t)k * strideK + n);
    float f[4] = {v.x, v.y, v.z, v.w};
    uint4 hv, lv;
    unsigned* hp = (unsigned*)&hv;
    unsigned* lp = (unsigned*)&lv;
    #pragma unroll
    for (int j = 0; j < 4; j++) {
        unsigned h = f2tf(f[j]);
        hp[j] = h;
        lp[j] = f2tf(f[j] - __uint_as_float(h));
    }
    *reinterpret_cast<uint4*>(&Bsh[k][n]) = hv;
    *reinterpret_cast<uint4*>(&Bsl[k][n]) = lv;
}

// Warp-level compute over one BK=16 staged tile. 3xTF32 compensated.
__device__ __forceinline__ void warp_mma_bk(
    float acc[2][4][4],
    const unsigned (*Ash)[ASTR], const unsigned (*Asl)[ASTR],
    const unsigned (*Bsh)[BSTR], const unsigned (*Bsl)[BSTR],
    int warpM, int warpN, int lane)
{
    int r = lane >> 2, t = lane & 3;
    #pragma unroll
    for (int ks = 0; ks < BK; ks += 8) {
        unsigned ah[2][4], al[2][4], bh[4][2], bl[4][2];
        #pragma unroll
        for (int mi = 0; mi < 2; mi++) {
            int m0 = warpM * 32 + mi * 16;
            ah[mi][0] = Ash[ks + t][m0 + r];
            ah[mi][1] = Ash[ks + t][m0 + r + 8];
            ah[mi][2] = Ash[ks + t + 4][m0 + r];
            ah[mi][3] = Ash[ks + t + 4][m0 + r + 8];
            al[mi][0] = Asl[ks + t][m0 + r];
            al[mi][1] = Asl[ks + t][m0 + r + 8];
            al[mi][2] = Asl[ks + t + 4][m0 + r];
            al[mi][3] = Asl[ks + t + 4][m0 + r + 8];
        }
        #pragma unroll
        for (int ni = 0; ni < 4; ni++) {
            int n0 = warpN * 32 + ni * 8;
            bh[ni][0] = Bsh[ks + t][n0 + r];
            bh[ni][1] = Bsh[ks + t + 4][n0 + r];
            bl[ni][0] = Bsl[ks + t][n0 + r];
            bl[ni][1] = Bsl[ks + t + 4][n0 + r];
        }
        #pragma unroll
        for (int mi = 0; mi < 2; mi++)
            #pragma unroll
            for (int ni = 0; ni < 4; ni++) {
                mma_tf32(acc[mi][ni], ah[mi], bh[ni]);
                mma_tf32(acc[mi][ni], ah[mi], bl[ni]);
                mma_tf32(acc[mi][ni], al[mi], bh[ni]);
            }
    }
}

// ---------------------------------------------------------------------------
// Y[M,N] = X[M,K] @ W[K,N] + b.   M=4096, N=1024, K=1024.
// grid = (N/BN, M/BM) = (16, 32)
// ---------------------------------------------------------------------------
__global__ __launch_bounds__(256) void gemm_bias_tc(
    const float* __restrict__ X, const float* __restrict__ W,
    const float* __restrict__ bias, float* __restrict__ Y)
{
    __shared__ unsigned Ash[BK][ASTR], Asl[BK][ASTR];
    __shared__ unsigned Bsh[BK][BSTR], Bsl[BK][BSTR];

    int tid = threadIdx.x, lane = tid & 31, warp = tid >> 5;
    int warpM = warp >> 1, warpN = warp & 1;
    int rowBase = blockIdx.y * BM;
    int colBase = blockIdx.x * BN;

    float acc[2][4][4] = {};

    for (int k0 = 0; k0 < D_MODEL; k0 += BK) {
        load_A_kcontig(X + (size_t)rowBase * D_MODEL + k0, D_MODEL, Ash, Asl, tid);
        load_B_ncontig(W + (size_t)k0 * D_MODEL + colBase, D_MODEL, Bsh, Bsl, tid);
        __syncthreads();
        warp_mma_bk(acc, Ash, Asl, Bsh, Bsl, warpM, warpN, lane);
        __syncthreads();
    }

    int r = lane >> 2, t = lane & 3;
    #pragma unroll
    for (int mi = 0; mi < 2; mi++) {
        int row0 = rowBase + warpM * 32 + mi * 16 + r;
        #pragma unroll
        for (int ni = 0; ni < 4; ni++) {
            int col = colBase + warpN * 32 + ni * 8 + t * 2;
            float2 b2 = *reinterpret_cast<const float2*>(&bias[col]);
            float2 v0 = {acc[mi][ni][0] + b2.x, acc[mi][ni][1] + b2.y};
            float2 v1 = {acc[mi][ni][2] + b2.x, acc[mi][ni][3] + b2.y};
            *reinterpret_cast<float2*>(&Y[(size_t)row0 * D_MODEL + col]) = v0;
            *reinterpret_cast<float2*>(&Y[(size_t)(row0 + 8) * D_MODEL + col]) = v1;
        }
    }
}

// ---------------------------------------------------------------------------
// scores: attn[b,h,q,s] = (Q_h[q,:] . K_h[s,:]) * 0.125
// grid = (SEQ/BN=32 s-tiles, SEQ/BM=16 q-tiles, 32 bh)
// ---------------------------------------------------------------------------
__global__ __launch_bounds__(256) void scores_tc(
    const float* __restrict__ Q, const float* __restrict__ Kmat,
    float* __restrict__ attn)
{
    __shared__ unsigned Ash[BK][ASTR], Asl[BK][ASTR];
    __shared__ unsigned Bsh[BK][BSTR], Bsl[BK][BSTR];

    int tid = threadIdx.x, lane = tid & 31, warp = tid >> 5;
    int warpM = warp >> 1, warpN = warp & 1;
    int sBase = blockIdx.x * BN;
    int qBase = blockIdx.y * BM;
    int bh = blockIdx.z;
    int b = bh >> 4, h = bh & 15;

    float acc[2][4][4] = {};

    #pragma unroll
    for (int k0 = 0; k0 < DK; k0 += BK) {
        load_A_kcontig(Q + ((size_t)(b * SEQ + qBase)) * D_MODEL + h * DK + k0,
                       D_MODEL, Ash, Asl, tid);
        load_B_kcontig(Kmat + ((size_t)(b * SEQ + sBase)) * D_MODEL + h * DK + k0,
                       D_MODEL, Bsh, Bsl, tid);
        __syncthreads();
        warp_mma_bk(acc, Ash, Asl, Bsh, Bsl, warpM, warpN, lane);
        __syncthreads();
    }

    const float scale = 0.125f;
    int r = lane >> 2, t = lane & 3;
    #pragma unroll
    for (int mi = 0; mi < 2; mi++) {
        int q0 = qBase + warpM * 32 + mi * 16 + r;
        #pragma unroll
        for (int ni = 0; ni < 4; ni++) {
            int s = sBase + warpN * 32 + ni * 8 + t * 2;
            float2 v0 = {acc[mi][ni][0] * scale, acc[mi][ni][1] * scale};
            float2 v1 = {acc[mi][ni][2] * scale, acc[mi][ni][3] * scale};
            *reinterpret_cast<float2*>(&attn[((size_t)bh * SEQ + q0) * SEQ + s]) = v0;
            *reinterpret_cast<float2*>(&attn[((size_t)bh * SEQ + q0 + 8) * SEQ + s]) = v1;
        }
    }
}

// ---------------------------------------------------------------------------
// ctx[b,q,h*64+n] = sum_s attn[b,h,q,s] * V[b,s,h*64+n]
// grid = (1, SEQ/BM=16, 32)
// ---------------------------------------------------------------------------
__global__ __launch_bounds__(256) void ctx_tc(
    const float* __restrict__ attn, const float* __restrict__ V,
    float* __restrict__ ctx)
{
    __shared__ unsigned Ash[BK][ASTR], Asl[BK][ASTR];
    __shared__ unsigned Bsh[BK][BSTR], Bsl[BK][BSTR];

    int tid = threadIdx.x, lane = tid & 31, warp = tid >> 5;
    int warpM = warp >> 1, warpN = warp & 1;
    int qBase = blockIdx.y * BM;
    int bh = blockIdx.z;
    int b = bh >> 4, h = bh & 15;

    float acc[2][4][4] = {};

    for (int k0 = 0; k0 < SEQ; k0 += BK) {
        load_A_kcontig(attn + ((size_t)bh * SEQ + qBase) * SEQ + k0, SEQ, Ash, Asl, tid);
        load_B_ncontig(V + ((size_t)(b * SEQ + k0)) * D_MODEL + h * DK, D_MODEL,
                       Bsh, Bsl, tid);
        __syncthreads();
        warp_mma_bk(acc, Ash, Asl, Bsh, Bsl, warpM, warpN, lane);
        __syncthreads();
    }

    int r = lane >> 2, t = lane & 3;
    #pragma unroll
    for (int mi = 0; mi < 2; mi++) {
        int q0 = qBase + warpM * 32 + mi * 16 + r;
        #pragma unroll
        for (int ni = 0; ni < 4; ni++) {
            int col = warpN * 32 + ni * 8 + t * 2;
            float2 v0 = {acc[mi][ni][0], acc[mi][ni][1]};
            float2 v1 = {acc[mi][ni][2], acc[mi][ni][3]};
            *reinterpret_cast<float2*>(
                &ctx[((size_t)(b * SEQ + q0)) * D_MODEL + h * DK + col]) = v0;
            *reinterpret_cast<float2*>(
                &ctx[((size_t)(b * SEQ + q0 + 8)) * D_MODEL + h * DK + col]) = v1;
        }
    }
}

// ---------------------------------------------------------------------------
// In-place row softmax over attn rows of length 2048. One block per row.
// ---------------------------------------------------------------------------
__global__ __launch_bounds__(256) void softmax_kernel(float* __restrict__ attn)
{
    size_t row = blockIdx.x;
    float* p = attn + row * SEQ;
    int tid = threadIdx.x;
    int lane = tid & 31, warp = tid >> 5;

    __shared__ float sred[8];

    float v[8];
    float mx = -INFINITY;
    #pragma unroll
    for (int i = 0; i < 8; i++) {
        v[i] = p[tid + i * 256];
        mx = fmaxf(mx, v[i]);
    }
    #pragma unroll
    for (int o = 16; o > 0; o >>= 1) mx = fmaxf(mx, __shfl_xor_sync(0xFFFFFFFFu, mx, o));
    if (lane == 0) sred[warp] = mx;
    __syncthreads();
    if (tid < 32) {
        float m = (tid < 8) ? sred[tid] : -INFINITY;
        #pragma unroll
        for (int o = 4; o > 0; o >>= 1) m = fmaxf(m, __shfl_xor_sync(0xFFFFFFFFu, m, o));
        if (tid == 0) sred[0] = m;
    }
    __syncthreads();
    mx = sred[0];
    __syncthreads();

    float sum = 0.0f;
    #pragma unroll
    for (int i = 0; i < 8; i++) {
        v[i] = __expf(v[i] - mx);
        sum += v[i];
    }
    #pragma unroll
    for (int o = 16; o > 0; o >>= 1) sum += __shfl_xor_sync(0xFFFFFFFFu, sum, o);
    if (lane == 0) sred[warp] = sum;
    __syncthreads();
    if (tid < 32) {
        float s = (tid < 8) ? sred[tid] : 0.0f;
        #pragma unroll
        for (int o = 4; o > 0; o >>= 1) s += __shfl_xor_sync(0xFFFFFFFFu, s, o);
        if (tid == 0) sred[0] = s;
    }
    __syncthreads();
    float inv = 1.0f / sred[0];

    #pragma unroll
    for (int i = 0; i < 8; i++) p[tid + i * 256] = v[i] * inv;
}

// ---------------------------------------------------------------------------
extern "C" void kernel_launch(void* const* d_in, const int* in_sizes, int n_in,
                              void* d_out, int out_size)
{
    const float* query = (const float*)d_in[0];
    const float* key   = (const float*)d_in[1];
    const float* value = (const float*)d_in[2];
    const float* Wq = (const float*)d_in[3];
    const float* bq = (const float*)d_in[4];
    const float* Wk = (const float*)d_in[5];
    const float* bk = (const float*)d_in[6];
    const float* Wv = (const float*)d_in[7];
    const float* bv = (const float*)d_in[8];
    const float* Wo = (const float*)d_in[9];
    const float* bo = (const float*)d_in[10];

    float* out  = (float*)d_out;
    float* attn = (float*)d_out + OUT_ELEMS;

    float* Qp; cudaGetSymbolAddress((void**)&Qp, g_Q);
    float* Kp; cudaGetSymbolAddress((void**)&Kp, g_K);
    float* Vp; cudaGetSymbolAddress((void**)&Vp, g_V);
    float* Cp; cudaGetSymbolAddress((void**)&Cp, g_ctx);

    dim3 gGemm(D_MODEL / BN, MROWS / BM);           // (16, 32)
    dim3 gScores(SEQ / BN, SEQ / BM, BATCH * NHEAD); // (32, 16, 32)
    dim3 gCtx(1, SEQ / BM, BATCH * NHEAD);           // (1, 16, 32)

    gemm_bias_tc<<<gGemm, 256>>>(query, Wq, bq, Qp);
    gemm_bias_tc<<<gGemm, 256>>>(key,   Wk, bk, Kp);
    gemm_bias_tc<<<gGemm, 256>>>(value, Wv, bv, Vp);

    scores_tc<<<gScores, 256>>>(Qp, Kp, attn);
    softmax_kernel<<<BATCH * NHEAD * SEQ, 256>>>(attn);
    ctx_tc<<<gCtx, 256>>>(attn, Vp, Cp);

    gemm_bias_tc<<<gGemm, 256>>>(Cp, Wo, bo, out);
}

// round 3
// speedup vs baseline: 2.0354x; 1.1348x over previous
#include <cuda_runtime.h>
#include <math.h>

#define D_MODEL 1024
#define NHEAD   16
#define DK      64
#define BATCH   2
#define SEQ     2048
#define MROWS   (BATCH * SEQ)
#define NBH     (BATCH * NHEAD)
#define OUT_ELEMS ((size_t)MROWS * D_MODEL)

// Scratch (no cudaMalloc allowed)
__device__ float g_Q[MROWS * D_MODEL];
__device__ float g_K[MROWS * D_MODEL];
__device__ float g_V[MROWS * D_MODEL];
__device__ float g_ctx[MROWS * D_MODEL];
__device__ float g_m[NBH * SEQ];
__device__ float g_s[NBH * SEQ];

// ---------------------------------------------------------------------------
__device__ __forceinline__ unsigned f2tf(float f) {
    unsigned u;
    asm("cvt.rna.tf32.f32 %0, %1;" : "=r"(u) : "f"(f));
    return u;
}

__device__ __forceinline__ void split_store(float f, unsigned* hp, unsigned* lp) {
    unsigned h = f2tf(f);
    *hp = h;
    *lp = f2tf(f - __uint_as_float(h));
}

__device__ __forceinline__ void mma_tf32(float* c, const unsigned* a, const unsigned* b) {
    asm volatile(
        "mma.sync.aligned.m16n8k8.row.col.f32.tf32.tf32.f32 "
        "{%0,%1,%2,%3},{%4,%5,%6,%7},{%8,%9},{%0,%1,%2,%3};"
        : "+f"(c[0]), "+f"(c[1]), "+f"(c[2]), "+f"(c[3])
        : "r"(a[0]), "r"(a[1]), "r"(a[2]), "r"(a[3]), "r"(b[0]), "r"(b[1]));
}

// Warp tile 64(m) x 32(n) over one BK=16 stage. 3xTF32 compensated: 96 MMAs.
template<int AS, int BS>
__device__ __forceinline__ void warp_mma16(
    float (*acc)[4][4],
    const unsigned (*Ash)[AS], const unsigned (*Asl)[AS],
    const unsigned (*Bsh)[BS], const unsigned (*Bsl)[BS],
    int m0base, int n0base, int lane)
{
    int r = lane >> 2, t = lane & 3;
    #pragma unroll
    for (int ks = 0; ks < 16; ks += 8) {
        unsigned ah[4][4], al[4][4], bh[4][2], bl[4][2];
        #pragma unroll
        for (int mi = 0; mi < 4; mi++) {
            int m0 = m0base + mi * 16 + r;
            ah[mi][0] = Ash[ks + t][m0];     ah[mi][1] = Ash[ks + t][m0 + 8];
            ah[mi][2] = Ash[ks + t + 4][m0]; ah[mi][3] = Ash[ks + t + 4][m0 + 8];
            al[mi][0] = Asl[ks + t][m0];     al[mi][1] = Asl[ks + t][m0 + 8];
            al[mi][2] = Asl[ks + t + 4][m0]; al[mi][3] = Asl[ks + t + 4][m0 + 8];
        }
        #pragma unroll
        for (int ni = 0; ni < 4; ni++) {
            int n0 = n0base + ni * 8 + r;
            bh[ni][0] = Bsh[ks + t][n0]; bh[ni][1] = Bsh[ks + t + 4][n0];
            bl[ni][0] = Bsl[ks + t][n0]; bl[ni][1] = Bsl[ks + t + 4][n0];
        }
        #pragma unroll
        for (int mi = 0; mi < 4; mi++)
            #pragma unroll
            for (int ni = 0; ni < 4; ni++) {
                mma_tf32(acc[mi][ni], ah[mi], bh[ni]);
                mma_tf32(acc[mi][ni], ah[mi], bl[ni]);
                mma_tf32(acc[mi][ni], al[mi], bh[ni]);
            }
    }
}

// ---------------------------------------------------------------------------
// Y[M,N] = X[M,K] @ W[K,N] + b.  BM=128, BN=128, BK=16. 8 warps (2m x 4n).
// grid = (N/128, M/128)
// ---------------------------------------------------------------------------
__global__ __launch_bounds__(256) void gemm_bias_tc(
    const float* __restrict__ X, const float* __restrict__ W,
    const float* __restrict__ bias, float* __restrict__ Y)
{
    __shared__ unsigned Ash[16][132], Asl[16][132];
    __shared__ unsigned Bsh[16][132], Bsl[16][132];

    int tid = threadIdx.x, lane = tid & 31, warp = tid >> 5;
    int warpM = warp >> 2, warpN = warp & 3;
    int rowBase = blockIdx.y * 128;
    int colBase = blockIdx.x * 128;

    const float* Xb = X + (size_t)rowBase * D_MODEL;
    const float* Wb = W + colBase;

    float acc[4][4][4] = {};
    float4 av[2], bv[2];

    #pragma unroll
    for (int i = 0; i < 2; i++) {
        int e = tid + i * 256;
        av[i] = *(const float4*)(Xb + (size_t)(e >> 2) * D_MODEL + (e & 3) * 4);
        bv[i] = *(const float4*)(Wb + (size_t)(e >> 5) * D_MODEL + (e & 31) * 4);
    }

    for (int k0 = 0; k0 < D_MODEL; k0 += 16) {
        #pragma unroll
        for (int i = 0; i < 2; i++) {
            int e = tid + i * 256;
            {
                int m = e >> 2, k = (e & 3) * 4;
                float f[4] = {av[i].x, av[i].y, av[i].z, av[i].w};
                #pragma unroll
                for (int j = 0; j < 4; j++) split_store(f[j], &Ash[k + j][m], &Asl[k + j][m]);
            }
            {
                int k = e >> 5, n = (e & 31) * 4;
                float f[4] = {bv[i].x, bv[i].y, bv[i].z, bv[i].w};
                uint4 hv, lv;
                unsigned* hp = (unsigned*)&hv; unsigned* lp = (unsigned*)&lv;
                #pragma unroll
                for (int j = 0; j < 4; j++) { unsigned h = f2tf(f[j]); hp[j] = h; lp[j] = f2tf(f[j] - __uint_as_float(h)); }
                *(uint4*)&Bsh[k][n] = hv;
                *(uint4*)&Bsl[k][n] = lv;
            }
        }
        __syncthreads();
        if (k0 + 16 < D_MODEL) {
            const float* Xn = Xb + k0 + 16;
            const float* Wn = Wb + (size_t)(k0 + 16) * D_MODEL;
            #pragma unroll
            for (int i = 0; i < 2; i++) {
                int e = tid + i * 256;
                av[i] = *(const float4*)(Xn + (size_t)(e >> 2) * D_MODEL + (e & 3) * 4);
                bv[i] = *(const float4*)(Wn + (size_t)(e >> 5) * D_MODEL + (e & 31) * 4);
            }
        }
        warp_mma16<132, 132>(acc, Ash, Asl, Bsh, Bsl, warpM * 64, warpN * 32, lane);
        __syncthreads();
    }

    int r = lane >> 2, t = lane & 3;
    #pragma unroll
    for (int mi = 0; mi < 4; mi++) {
        int row0 = rowBase + warpM * 64 + mi * 16 + r;
        #pragma unroll
        for (int ni = 0; ni < 4; ni++) {
            int col = colBase + warpN * 32 + ni * 8 + t * 2;
            float2 b2 = *(const float2*)&bias[col];
            float2 v0 = {acc[mi][ni][0] + b2.x, acc[mi][ni][1] + b2.y};
            float2 v1 = {acc[mi][ni][2] + b2.x, acc[mi][ni][3] + b2.y};
            *(float2*)&Y[(size_t)row0 * D_MODEL + col] = v0;
            *(float2*)&Y[(size_t)(row0 + 8) * D_MODEL + col] = v1;
        }
    }
}

// ---------------------------------------------------------------------------
// scores + online row stats. One block per (q-tile 128, bh); iterates all 16
// s-tiles of 128. Q tile hoisted into smem once. Writes RAW scaled scores to
// attn, and per-row (max, sumexp) to g_m/g_s.
// Dynamic smem: Qh/Ql 64x132, Bsh/Bsl 16x132, RedM/RedS 4x128.
// ---------------------------------------------------------------------------
#define SC_QH_OFF   0
#define SC_QL_OFF   (64 * 132)
#define SC_BH_OFF   (2 * 64 * 132)
#define SC_BL_OFF   (2 * 64 * 132 + 16 * 132)
#define SC_RM_OFF   (2 * 64 * 132 + 2 * 16 * 132)
#define SC_RS_OFF   (SC_RM_OFF + 4 * 128)
#define SC_SMEM_BYTES ((SC_RS_OFF + 4 * 128) * 4)

__global__ __launch_bounds__(256) void scores_tc(
    const float* __restrict__ Q, const float* __restrict__ Kmat,
    float* __restrict__ attn)
{
    extern __shared__ unsigned sm_u[];
    unsigned (*Qh)[132]  = (unsigned(*)[132])(sm_u + SC_QH_OFF);
    unsigned (*Ql)[132]  = (unsigned(*)[132])(sm_u + SC_QL_OFF);
    unsigned (*Bsh)[132] = (unsigned(*)[132])(sm_u + SC_BH_OFF);
    unsigned (*Bsl)[132] = (unsigned(*)[132])(sm_u + SC_BL_OFF);
    float (*RedM)[128] = (float(*)[128])(sm_u + SC_RM_OFF);
    float (*RedS)[128] = (float(*)[128])(sm_u + SC_RS_OFF);

    int tid = threadIdx.x, lane = tid & 31, warp = tid >> 5;
    int warpM = warp >> 2, warpN = warp & 3;
    int qBase = blockIdx.x * 128;
    int bh = blockIdx.y, b = bh >> 4, h = bh & 15;
    int r = lane >> 2, t = lane & 3;

    const float* Qb  = Q    + ((size_t)(b * SEQ + qBase)) * D_MODEL + h * DK;
    const float* Kb0 = Kmat + ((size_t)(b * SEQ))         * D_MODEL + h * DK;

    // Hoist full 128x64 Q tile (hi/lo) into smem.
    #pragma unroll
    for (int i = 0; i < 8; i++) {
        int e = tid + i * 256;            // 0..2047
        int m = e >> 4, k = (e & 15) * 4;
        float4 v = *(const float4*)(Qb + (size_t)m * D_MODEL + k);
        float f[4] = {v.x, v.y, v.z, v.w};
        #pragma unroll
        for (int j = 0; j < 4; j++) split_store(f[j], &Qh[k + j][m], &Ql[k + j][m]);
    }
    __syncthreads();

    float rm[8], rs[8];
    #pragma unroll
    for (int j = 0; j < 8; j++) { rm[j] = -INFINITY; rs[j] = 0.0f; }

    float4 bv[2];
    #pragma unroll
    for (int i = 0; i < 2; i++) {
        int e = tid + i * 256;
        bv[i] = *(const float4*)(Kb0 + (size_t)(e >> 2) * D_MODEL + (e & 3) * 4);
    }

    const float scale = 0.125f;

    for (int st = 0; st < 16; st++) {
        int sBase = st * 128;
        float acc[4][4][4] = {};

        #pragma unroll
        for (int kk = 0; kk < 4; kk++) {
            #pragma unroll
            for (int i = 0; i < 2; i++) {
                int e = tid + i * 256;
                int n = e >> 2, k = (e & 3) * 4;
                float f[4] = {bv[i].x, bv[i].y, bv[i].z, bv[i].w};
                #pragma unroll
                for (int j = 0; j < 4; j++) split_store(f[j], &Bsh[k + j][n], &Bsl[k + j][n]);
            }
            __syncthreads();
            {
                int nst = st, nkk = kk + 1;
                if (nkk == 4) { nkk = 0; nst = st + 1; }
                if (nst < 16) {
                    const float* Kb = Kb0 + (size_t)(nst * 128) * D_MODEL + nkk * 16;
                    #pragma unroll
                    for (int i = 0; i < 2; i++) {
                        int e = tid + i * 256;
                        bv[i] = *(const float4*)(Kb + (size_t)(e >> 2) * D_MODEL + (e & 3) * 4);
                    }
                }
            }
            warp_mma16<132, 132>(acc, (const unsigned(*)[132])&Qh[kk * 16],
                                 (const unsigned(*)[132])&Ql[kk * 16],
                                 Bsh, Bsl, warpM * 64, warpN * 32, lane);
            __syncthreads();
        }

        // Epilogue: scale, write raw, update online stats.
        #pragma unroll
        for (int mi = 0; mi < 4; mi++) {
            #pragma unroll
            for (int hh = 0; hh < 2; hh++) {
                int row = qBase + warpM * 64 + mi * 16 + hh * 8 + r;
                size_t rowOff = ((size_t)bh * SEQ + row) * SEQ;
                int j = mi * 2 + hh;
                float vals[8];
                float vmax = -INFINITY;
                #pragma unroll
                for (int ni = 0; ni < 4; ni++) {
                    float v0 = acc[mi][ni][hh * 2 + 0] * scale;
                    float v1 = acc[mi][ni][hh * 2 + 1] * scale;
                    vals[ni * 2] = v0; vals[ni * 2 + 1] = v1;
                    int col = sBase + warpN * 32 + ni * 8 + t * 2;
                    *(float2*)&attn[rowOff + col] = make_float2(v0, v1);
                    vmax = fmaxf(vmax, fmaxf(v0, v1));
                }
                float nm = fmaxf(rm[j], vmax);
                float add = 0.0f;
                #pragma unroll
                for (int i = 0; i < 8; i++) add += __expf(vals[i] - nm);
                rs[j] = rs[j] * __expf(rm[j] - nm) + add;
                rm[j] = nm;
            }
        }
    }

    // Reduce stats across the 4 t-lanes sharing each row.
    #pragma unroll
    for (int off = 1; off <= 2; off <<= 1) {
        #pragma unroll
        for (int j = 0; j < 8; j++) {
            float om = __shfl_xor_sync(0xFFFFFFFFu, rm[j], off);
            float os = __shfl_xor_sync(0xFFFFFFFFu, rs[j], off);
            float nm = fmaxf(rm[j], om);
            rs[j] = rs[j] * __expf(rm[j] - nm) + os * __expf(om - nm);
            rm[j] = nm;
        }
    }
    if (t == 0) {
        #pragma unroll
        for (int mi = 0; mi < 4; mi++)
            #pragma unroll
            for (int hh = 0; hh < 2; hh++) {
                int row = warpM * 64 + mi * 16 + hh * 8 + r;
                RedM[warpN][row] = rm[mi * 2 + hh];
                RedS[warpN][row] = rs[mi * 2 + hh];
            }
    }
    __syncthreads();
    if (tid < 128) {
        float m0 = RedM[0][tid], m1 = RedM[1][tid], m2 = RedM[2][tid], m3 = RedM[3][tid];
        float nm = fmaxf(fmaxf(m0, m1), fmaxf(m2, m3));
        float s = RedS[0][tid] * __expf(m0 - nm) + RedS[1][tid] * __expf(m1 - nm)
                + RedS[2][tid] * __expf(m2 - nm) + RedS[3][tid] * __expf(m3 - nm);
        g_m[(size_t)bh * SEQ + qBase + tid] = nm;
        g_s[(size_t)bh * SEQ + qBase + tid] = s;
    }
}

// ---------------------------------------------------------------------------
// ctx: reads raw scores, normalizes (exp(x-m)/s), writes normalized attn back,
// and computes ctx = P @ V.  BM=256(q), BN=64(dk), BK=16(s). 8 warps (4m x 2n).
// grid = (SEQ/256, NBH)
// ---------------------------------------------------------------------------
__global__ __launch_bounds__(256) void ctx_tc(
    float* __restrict__ attn, const float* __restrict__ V,
    float* __restrict__ ctx)
{
    __shared__ unsigned Ash[16][260], Asl[16][260];
    __shared__ unsigned Bsh[16][68], Bsl[16][68];
    __shared__ float smM[256], smI[256];

    int tid = threadIdx.x, lane = tid & 31, warp = tid >> 5;
    int warpM = warp >> 1, warpN = warp & 1;
    int qBase = blockIdx.x * 256;
    int bh = blockIdx.y, b = bh >> 4, h = bh & 15;
    int r = lane >> 2, t = lane & 3;

    smM[tid] = g_m[(size_t)bh * SEQ + qBase + tid];
    smI[tid] = 1.0f / g_s[(size_t)bh * SEQ + qBase + tid];
    __syncthreads();

    float* Ab = attn + ((size_t)bh * SEQ + qBase) * SEQ;
    const float* Vb = V + ((size_t)(b * SEQ)) * D_MODEL + h * DK;

    float acc[4][4][4] = {};
    float4 av[4], bvv;

    #pragma unroll
    for (int i = 0; i < 4; i++) {
        int e = tid + i * 256;
        av[i] = *(const float4*)(Ab + (size_t)(e >> 2) * SEQ + (e & 3) * 4);
    }
    bvv = *(const float4*)(Vb + (size_t)(tid >> 4) * D_MODEL + (tid & 15) * 4);

    for (int k0 = 0; k0 < SEQ; k0 += 16) {
        #pragma unroll
        for (int i = 0; i < 4; i++) {
            int e = tid + i * 256;
            int m = e >> 2, k = (e & 3) * 4;
            float mM = smM[m], mI = smI[m];
            float p0 = __expf(av[i].x - mM) * mI;
            float p1 = __expf(av[i].y - mM) * mI;
            float p2 = __expf(av[i].z - mM) * mI;
            float p3 = __expf(av[i].w - mM) * mI;
            *(float4*)(Ab + (size_t)m * SEQ + k0 + k) = make_float4(p0, p1, p2, p3);
            split_store(p0, &Ash[k + 0][m], &Asl[k + 0][m]);
            split_store(p1, &Ash[k + 1][m], &Asl[k + 1][m]);
            split_store(p2, &Ash[k + 2][m], &Asl[k + 2][m]);
            split_store(p3, &Ash[k + 3][m], &Asl[k + 3][m]);
        }
        {
            int k = tid >> 4, n = (tid & 15) * 4;
            float f[4] = {bvv.x, bvv.y, bvv.z, bvv.w};
            uint4 hv, lv;
            unsigned* hp = (unsigned*)&hv; unsigned* lp = (unsigned*)&lv;
            #pragma unroll
            for (int j = 0; j < 4; j++) { unsigned hb = f2tf(f[j]); hp[j] = hb; lp[j] = f2tf(f[j] - __uint_as_float(hb)); }
            *(uint4*)&Bsh[k][n] = hv;
            *(uint4*)&Bsl[k][n] = lv;
        }
        __syncthreads();
        if (k0 + 16 < SEQ) {
            #pragma unroll
            for (int i = 0; i < 4; i++) {
                int e = tid + i * 256;
                av[i] = *(const float4*)(Ab + (size_t)(e >> 2) * SEQ + k0 + 16 + (e & 3) * 4);
            }
            bvv = *(const float4*)(Vb + (size_t)(k0 + 16 + (tid >> 4)) * D_MODEL + (tid & 15) * 4);
        }
        warp_mma16<260, 68>(acc, Ash, Asl, Bsh, Bsl, warpM * 64, warpN * 32, lane);
        __syncthreads();
    }

    #pragma unroll
    for (int mi = 0; mi < 4; mi++) {
        int q0 = qBase + warpM * 64 + mi * 16 + r;
        #pragma unroll
        for (int ni = 0; ni < 4; ni++) {
            int col = warpN * 32 + ni * 8 + t * 2;
            float2 v0 = {acc[mi][ni][0], acc[mi][ni][1]};
            float2 v1 = {acc[mi][ni][2], acc[mi][ni][3]};
            *(float2*)&ctx[((size_t)(b * SEQ + q0)) * D_MODEL + h * DK + col] = v0;
            *(float2*)&ctx[((size_t)(b * SEQ + q0 + 8)) * D_MODEL + h * DK + col] = v1;
        }
    }
}

// ---------------------------------------------------------------------------
extern "C" void kernel_launch(void* const* d_in, const int* in_sizes, int n_in,
                              void* d_out, int out_size)
{
    const float* query = (const float*)d_in[0];
    const float* key   = (const float*)d_in[1];
    const float* value = (const float*)d_in[2];
    const float* Wq = (const float*)d_in[3];
    const float* bq = (const float*)d_in[4];
    const float* Wk = (const float*)d_in[5];
    const float* bk = (const float*)d_in[6];
    const float* Wv = (const float*)d_in[7];
    const float* bv = (const float*)d_in[8];
    const float* Wo = (const float*)d_in[9];
    const float* bo = (const float*)d_in[10];

    float* out  = (float*)d_out;
    float* attn = (float*)d_out + OUT_ELEMS;

    float* Qp; cudaGetSymbolAddress((void**)&Qp, g_Q);
    float* Kp; cudaGetSymbolAddress((void**)&Kp, g_K);
    float* Vp; cudaGetSymbolAddress((void**)&Vp, g_V);
    float* Cp; cudaGetSymbolAddress((void**)&Cp, g_ctx);

    static int configured = 0;
    if (!configured) {
        cudaFuncSetAttribute(scores_tc, cudaFuncAttributeMaxDynamicSharedMemorySize,
                             SC_SMEM_BYTES);
        configured = 1;
    }

    dim3 gProj(D_MODEL / 128, MROWS / 128);   // (8, 32)
    dim3 gScores(SEQ / 128, NBH);             // (16, 32)
    dim3 gCtx(SEQ / 256, NBH);                // (8, 32)

    gemm_bias_tc<<<gProj, 256>>>(query, Wq, bq, Qp);
    gemm_bias_tc<<<gProj, 256>>>(key,   Wk, bk, Kp);
    gemm_bias_tc<<<gProj, 256>>>(value, Wv, bv, Vp);

    scores_tc<<<gScores, 256, SC_SMEM_BYTES>>>(Qp, Kp, attn);
    ctx_tc<<<gCtx, 256>>>(attn, Vp, Cp);

    gemm_bias_tc<<<gProj, 256>>>(Cp, Wo, bo, out);
}

// round 4
// speedup vs baseline: 2.2827x; 1.1215x over previous
#include <cuda_runtime.h>
#include <math.h>

#define D_MODEL 1024
#define NHEAD   16
#define DK      64
#define BATCH   2
#define SEQ     2048
#define MROWS   (BATCH * SEQ)
#define NBH     (BATCH * NHEAD)
#define OUT_ELEMS ((size_t)MROWS * D_MODEL)

// Scratch (no cudaMalloc allowed)
__device__ float g_Q[MROWS * D_MODEL];
__device__ float g_K[MROWS * D_MODEL];
__device__ float g_V[MROWS * D_MODEL];
__device__ float g_ctx[MROWS * D_MODEL];
__device__ float g_s[NBH * SEQ];

// ---------------------------------------------------------------------------
__device__ __forceinline__ unsigned f2tf(float f) {
    unsigned u;
    asm("cvt.rna.tf32.f32 %0, %1;" : "=r"(u) : "f"(f));
    return u;
}

__device__ __forceinline__ void split_store(float f, unsigned* hp, unsigned* lp) {
    unsigned h = f2tf(f);
    *hp = h;
    *lp = f2tf(f - __uint_as_float(h));
}

__device__ __forceinline__ void mma_tf32(float* c, const unsigned* a, const unsigned* b) {
    asm volatile(
        "mma.sync.aligned.m16n8k8.row.col.f32.tf32.tf32.f32 "
        "{%0,%1,%2,%3},{%4,%5,%6,%7},{%8,%9},{%0,%1,%2,%3};"
        : "+f"(c[0]), "+f"(c[1]), "+f"(c[2]), "+f"(c[3])
        : "r"(a[0]), "r"(a[1]), "r"(a[2]), "r"(a[3]), "r"(b[0]), "r"(b[1]));
}

// Warp tile 64(m) x 32(n) over one BK=16 stage. 3xTF32 compensated: 96 MMAs.
template<int AS, int BS>
__device__ __forceinline__ void warp_mma16(
    float (*acc)[4][4],
    const unsigned (*Ash)[AS], const unsigned (*Asl)[AS],
    const unsigned (*Bsh)[BS], const unsigned (*Bsl)[BS],
    int m0base, int n0base, int lane)
{
    int r = lane >> 2, t = lane & 3;
    #pragma unroll
    for (int ks = 0; ks < 16; ks += 8) {
        unsigned ah[4][4], al[4][4], bh[4][2], bl[4][2];
        #pragma unroll
        for (int mi = 0; mi < 4; mi++) {
            int m0 = m0base + mi * 16 + r;
            ah[mi][0] = Ash[ks + t][m0];     ah[mi][1] = Ash[ks + t][m0 + 8];
            ah[mi][2] = Ash[ks + t + 4][m0]; ah[mi][3] = Ash[ks + t + 4][m0 + 8];
            al[mi][0] = Asl[ks + t][m0];     al[mi][1] = Asl[ks + t][m0 + 8];
            al[mi][2] = Asl[ks + t + 4][m0]; al[mi][3] = Asl[ks + t + 4][m0 + 8];
        }
        #pragma unroll
        for (int ni = 0; ni < 4; ni++) {
            int n0 = n0base + ni * 8 + r;
            bh[ni][0] = Bsh[ks + t][n0]; bh[ni][1] = Bsh[ks + t + 4][n0];
            bl[ni][0] = Bsl[ks + t][n0]; bl[ni][1] = Bsl[ks + t + 4][n0];
        }
        #pragma unroll
        for (int mi = 0; mi < 4; mi++)
            #pragma unroll
            for (int ni = 0; ni < 4; ni++) {
                mma_tf32(acc[mi][ni], ah[mi], bh[ni]);
                mma_tf32(acc[mi][ni], ah[mi], bl[ni]);
                mma_tf32(acc[mi][ni], al[mi], bh[ni]);
            }
    }
}

// ---------------------------------------------------------------------------
// Projection GEMM: Y = X @ W + b.  BM=128, BN=128, BK=16, double-buffered.
// Dynamic smem: per buffer [Ah 16x132, Al, Bh 16x132, Bl] = 8448 units; 2 bufs.
// ---------------------------------------------------------------------------
#define PROJ_SMEM_BYTES (2 * 8448 * 4)

__global__ __launch_bounds__(256) void gemm_bias_tc(
    const float* __restrict__ X, const float* __restrict__ W,
    const float* __restrict__ bias, float* __restrict__ Y)
{
    extern __shared__ unsigned sm[];

    int tid = threadIdx.x, lane = tid & 31, warp = tid >> 5;
    int warpM = warp >> 2, warpN = warp & 3;
    int rowBase = blockIdx.y * 128;
    int colBase = blockIdx.x * 128;

    const float* Xb = X + (size_t)rowBase * D_MODEL;
    const float* Wb = W + colBase;

    float acc[4][4][4] = {};
    float4 av[2], bv[2];

    #pragma unroll
    for (int i = 0; i < 2; i++) {
        int e = tid + i * 256;
        av[i] = *(const float4*)(Xb + (size_t)(e >> 2) * D_MODEL + (e & 3) * 4);
        bv[i] = *(const float4*)(Wb + (size_t)(e >> 5) * D_MODEL + (e & 31) * 4);
    }

    auto store_stage = [&](int b) {
        unsigned* base = sm + b * 8448;
        unsigned (*Ah)[132] = (unsigned(*)[132])(base);
        unsigned (*Al)[132] = (unsigned(*)[132])(base + 2112);
        unsigned (*Bh)[132] = (unsigned(*)[132])(base + 4224);
        unsigned (*Bl)[132] = (unsigned(*)[132])(base + 6336);
        #pragma unroll
        for (int i = 0; i < 2; i++) {
            int e = tid + i * 256;
            {
                int m = e >> 2, k = (e & 3) * 4;
                float f[4] = {av[i].x, av[i].y, av[i].z, av[i].w};
                #pragma unroll
                for (int j = 0; j < 4; j++) split_store(f[j], &Ah[k + j][m], &Al[k + j][m]);
            }
            {
                int k = e >> 5, n = (e & 31) * 4;
                float f[4] = {bv[i].x, bv[i].y, bv[i].z, bv[i].w};
                uint4 hv, lv;
                unsigned* hp = (unsigned*)&hv; unsigned* lp = (unsigned*)&lv;
                #pragma unroll
                for (int j = 0; j < 4; j++) { unsigned h = f2tf(f[j]); hp[j] = h; lp[j] = f2tf(f[j] - __uint_as_float(h)); }
                *(uint4*)&Bh[k][n] = hv;
                *(uint4*)&Bl[k][n] = lv;
            }
        }
    };

    store_stage(0);
    __syncthreads();

    const int NST = D_MODEL / 16;   // 64
    for (int s = 0; s < NST; s++) {
        int cur = s & 1;
        if (s + 1 < NST) {
            const float* Xn = Xb + (s + 1) * 16;
            const float* Wn = Wb + (size_t)((s + 1) * 16) * D_MODEL;
            #pragma unroll
            for (int i = 0; i < 2; i++) {
                int e = tid + i * 256;
                av[i] = *(const float4*)(Xn + (size_t)(e >> 2) * D_MODEL + (e & 3) * 4);
                bv[i] = *(const float4*)(Wn + (size_t)(e >> 5) * D_MODEL + (e & 31) * 4);
            }
        }
        unsigned* base = sm + cur * 8448;
        warp_mma16<132, 132>(acc,
            (const unsigned(*)[132])(base),
            (const unsigned(*)[132])(base + 2112),
            (const unsigned(*)[132])(base + 4224),
            (const unsigned(*)[132])(base + 6336),
            warpM * 64, warpN * 32, lane);
        if (s + 1 < NST) store_stage(cur ^ 1);
        __syncthreads();
    }

    int r = lane >> 2, t = lane & 3;
    #pragma unroll
    for (int mi = 0; mi < 4; mi++) {
        int row0 = rowBase + warpM * 64 + mi * 16 + r;
        #pragma unroll
        for (int ni = 0; ni < 4; ni++) {
            int col = colBase + warpN * 32 + ni * 8 + t * 2;
            float2 b2 = *(const float2*)&bias[col];
            float2 v0 = {acc[mi][ni][0] + b2.x, acc[mi][ni][1] + b2.y};
            float2 v1 = {acc[mi][ni][2] + b2.x, acc[mi][ni][3] + b2.y};
            *(float2*)&Y[(size_t)row0 * D_MODEL + col] = v0;
            *(float2*)&Y[(size_t)(row0 + 8) * D_MODEL + col] = v1;
        }
    }
}

// ---------------------------------------------------------------------------
// scores: writes e = exp(score) (no max subtraction; scores bounded) plus
// per-row sum-of-exp to g_s. Q tile hoisted; K tiles double-buffered.
// smem units: Qh 8448 | Ql 8448 | Kbufs 2*4224 | RedS 512
// ---------------------------------------------------------------------------
#define SC_K_OFF    16896
#define SC_RS_OFF   (16896 + 8448)
#define SC_SMEM_BYTES ((SC_RS_OFF + 512) * 4)

__global__ __launch_bounds__(256) void scores_tc(
    const float* __restrict__ Q, const float* __restrict__ Kmat,
    float* __restrict__ attn)
{
    extern __shared__ unsigned sm[];
    unsigned (*Qh)[132] = (unsigned(*)[132])(sm);
    unsigned (*Ql)[132] = (unsigned(*)[132])(sm + 8448);
    unsigned* kb = sm + SC_K_OFF;
    float (*RedS)[128] = (float(*)[128])(sm + SC_RS_OFF);

    int tid = threadIdx.x, lane = tid & 31, warp = tid >> 5;
    int warpM = warp >> 2, warpN = warp & 3;
    int qBase = blockIdx.x * 128;
    int bh = blockIdx.y, b = bh >> 4, h = bh & 15;
    int r = lane >> 2, t = lane & 3;

    const float* Qb  = Q    + ((size_t)(b * SEQ + qBase)) * D_MODEL + h * DK;
    const float* Kb0 = Kmat + ((size_t)(b * SEQ))         * D_MODEL + h * DK;

    // Hoist full 128x64 Q tile (hi/lo) into smem.
    #pragma unroll
    for (int i = 0; i < 8; i++) {
        int e = tid + i * 256;
        int m = e >> 4, k = (e & 15) * 4;
        float4 v = *(const float4*)(Qb + (size_t)m * D_MODEL + k);
        float f[4] = {v.x, v.y, v.z, v.w};
        #pragma unroll
        for (int j = 0; j < 4; j++) split_store(f[j], &Qh[k + j][m], &Ql[k + j][m]);
    }

    float4 bv[2];
    #pragma unroll
    for (int i = 0; i < 2; i++) {
        int e = tid + i * 256;
        bv[i] = *(const float4*)(Kb0 + (size_t)(e >> 2) * D_MODEL + (e & 3) * 4);
    }

    auto kstore = [&](int buf) {
        unsigned (*Bh)[132] = (unsigned(*)[132])(kb + buf * 4224);
        unsigned (*Bl)[132] = (unsigned(*)[132])(kb + buf * 4224 + 2112);
        #pragma unroll
        for (int i = 0; i < 2; i++) {
            int e = tid + i * 256;
            int n = e >> 2, k = (e & 3) * 4;
            float f[4] = {bv[i].x, bv[i].y, bv[i].z, bv[i].w};
            #pragma unroll
            for (int j = 0; j < 4; j++) split_store(f[j], &Bh[k + j][n], &Bl[k + j][n]);
        }
    };

    kstore(0);
    __syncthreads();

    float rs[8];
    #pragma unroll
    for (int j = 0; j < 8; j++) rs[j] = 0.0f;

    const float scale = 0.125f;
    const int NSTAGE = 64;   // 16 s-tiles x 4 k-chunks

    for (int st = 0; st < 16; st++) {
        int sBase = st * 128;
        float acc[4][4][4] = {};

        #pragma unroll
        for (int kk = 0; kk < 4; kk++) {
            int stage = st * 4 + kk;
            int cur = stage & 1;
            if (stage + 1 < NSTAGE) {
                int nst = (stage + 1) >> 2, nkk = (stage + 1) & 3;
                const float* Kb = Kb0 + (size_t)(nst * 128) * D_MODEL + nkk * 16;
                #pragma unroll
                for (int i = 0; i < 2; i++) {
                    int e = tid + i * 256;
                    bv[i] = *(const float4*)(Kb + (size_t)(e >> 2) * D_MODEL + (e & 3) * 4);
                }
            }
            warp_mma16<132, 132>(acc,
                (const unsigned(*)[132])&Qh[kk * 16],
                (const unsigned(*)[132])&Ql[kk * 16],
                (const unsigned(*)[132])(kb + cur * 4224),
                (const unsigned(*)[132])(kb + cur * 4224 + 2112),
                warpM * 64, warpN * 32, lane);
            if (stage + 1 < NSTAGE) kstore(cur ^ 1);
            __syncthreads();
        }

        // Epilogue: e = exp(score), write, accumulate row sums.
        #pragma unroll
        for (int mi = 0; mi < 4; mi++) {
            #pragma unroll
            for (int hh = 0; hh < 2; hh++) {
                int row = qBase + warpM * 64 + mi * 16 + hh * 8 + r;
                size_t rowOff = ((size_t)bh * SEQ + row) * SEQ;
                int j = mi * 2 + hh;
                float add = 0.0f;
                #pragma unroll
                for (int ni = 0; ni < 4; ni++) {
                    float e0 = __expf(acc[mi][ni][hh * 2 + 0] * scale);
                    float e1 = __expf(acc[mi][ni][hh * 2 + 1] * scale);
                    int col = sBase + warpN * 32 + ni * 8 + t * 2;
                    *(float2*)&attn[rowOff + col] = make_float2(e0, e1);
                    add += e0 + e1;
                }
                rs[j] += add;
            }
        }
    }

    // Reduce sums across the 4 t-lanes sharing each row.
    #pragma unroll
    for (int off = 1; off <= 2; off <<= 1)
        #pragma unroll
        for (int j = 0; j < 8; j++)
            rs[j] += __shfl_xor_sync(0xFFFFFFFFu, rs[j], off);
    if (t == 0) {
        #pragma unroll
        for (int mi = 0; mi < 4; mi++)
            #pragma unroll
            for (int hh = 0; hh < 2; hh++) {
                int row = warpM * 64 + mi * 16 + hh * 8 + r;
                RedS[warpN][row] = rs[mi * 2 + hh];
            }
    }
    __syncthreads();
    if (tid < 128) {
        float s = RedS[0][tid] + RedS[1][tid] + RedS[2][tid] + RedS[3][tid];
        g_s[(size_t)bh * SEQ + qBase + tid] = s;
    }
}

// ---------------------------------------------------------------------------
// ctx: reads e, normalizes p = e / s (writes normalized attn), ctx = P @ V.
// BM=256(q), BN=64(dk), BK=16(s), double-buffered. 8 warps (4m x 2n).
// smem units per buffer: Ah 4160 | Al 4160 | Bh 1088 | Bl 1088 = 10496; 2 bufs;
// smI 256 at +20992.
// ---------------------------------------------------------------------------
#define CTX_SMI_OFF 20992
#define CTX_SMEM_BYTES ((CTX_SMI_OFF + 256) * 4)

__global__ __launch_bounds__(256) void ctx_tc(
    float* __restrict__ attn, const float* __restrict__ V,
    float* __restrict__ ctx)
{
    extern __shared__ unsigned sm[];
    float* smI = (float*)(sm + CTX_SMI_OFF);

    int tid = threadIdx.x, lane = tid & 31, warp = tid >> 5;
    int warpM = warp >> 1, warpN = warp & 1;
    int qBase = blockIdx.x * 256;
    int bh = blockIdx.y, b = bh >> 4, h = bh & 15;
    int r = lane >> 2, t = lane & 3;

    smI[tid] = 1.0f / g_s[(size_t)bh * SEQ + qBase + tid];

    float* Ab = attn + ((size_t)bh * SEQ + qBase) * SEQ;
    const float* Vb = V + ((size_t)(b * SEQ)) * D_MODEL + h * DK;

    float acc[4][4][4] = {};
    float4 av[4], bvv;

    #pragma unroll
    for (int i = 0; i < 4; i++) {
        int e = tid + i * 256;
        av[i] = *(const float4*)(Ab + (size_t)(e >> 2) * SEQ + (e & 3) * 4);
    }
    bvv = *(const float4*)(Vb + (size_t)(tid >> 4) * D_MODEL + (tid & 15) * 4);
    __syncthreads();   // smI visible

    // Store stage `kpos` (element offset kpos*16 in s): normalize + write attn.
    auto store_stage = [&](int buf, int kpos) {
        unsigned* base = sm + buf * 10496;
        unsigned (*Ah)[260] = (unsigned(*)[260])(base);
        unsigned (*Al)[260] = (unsigned(*)[260])(base + 4160);
        unsigned (*Bh)[68]  = (unsigned(*)[68])(base + 8320);
        unsigned (*Bl)[68]  = (unsigned(*)[68])(base + 9408);
        #pragma unroll
        for (int i = 0; i < 4; i++) {
            int e = tid + i * 256;
            int m = e >> 2, k = (e & 3) * 4;
            float mI = smI[m];
            float p0 = av[i].x * mI, p1 = av[i].y * mI;
            float p2 = av[i].z * mI, p3 = av[i].w * mI;
            *(float4*)(Ab + (size_t)m * SEQ + kpos * 16 + k) = make_float4(p0, p1, p2, p3);
            split_store(p0, &Ah[k + 0][m], &Al[k + 0][m]);
            split_store(p1, &Ah[k + 1][m], &Al[k + 1][m]);
            split_store(p2, &Ah[k + 2][m], &Al[k + 2][m]);
            split_store(p3, &Ah[k + 3][m], &Al[k + 3][m]);
        }
        {
            int k = tid >> 4, n = (tid & 15) * 4;
            float f[4] = {bvv.x, bvv.y, bvv.z, bvv.w};
            uint4 hv, lv;
            unsigned* hp = (unsigned*)&hv; unsigned* lp = (unsigned*)&lv;
            #pragma unroll
            for (int j = 0; j < 4; j++) { unsigned hb = f2tf(f[j]); hp[j] = hb; lp[j] = f2tf(f[j] - __uint_as_float(hb)); }
            *(uint4*)&Bh[k][n] = hv;
            *(uint4*)&Bl[k][n] = lv;
        }
    };

    store_stage(0, 0);
    __syncthreads();

    const int NST = SEQ / 16;   // 128
    for (int s = 0; s < NST; s++) {
        int cur = s & 1;
        if (s + 1 < NST) {
            int k0 = (s + 1) * 16;
            #pragma unroll
            for (int i = 0; i < 4; i++) {
                int e = tid + i * 256;
                av[i] = *(const float4*)(Ab + (size_t)(e >> 2) * SEQ + k0 + (e & 3) * 4);
            }
            bvv = *(const float4*)(Vb + (size_t)(k0 + (tid >> 4)) * D_MODEL + (tid & 15) * 4);
        }
        unsigned* base = sm + cur * 10496;
        warp_mma16<260, 68>(acc,
            (const unsigned(*)[260])(base),
            (const unsigned(*)[260])(base + 4160),
            (const unsigned(*)[68])(base + 8320),
            (const unsigned(*)[68])(base + 9408),
            warpM * 64, warpN * 32, lane);
        if (s + 1 < NST) store_stage(cur ^ 1, s + 1);
        __syncthreads();
    }

    #pragma unroll
    for (int mi = 0; mi < 4; mi++) {
        int q0 = qBase + warpM * 64 + mi * 16 + r;
        #pragma unroll
        for (int ni = 0; ni < 4; ni++) {
            int col = warpN * 32 + ni * 8 + t * 2;
            float2 v0 = {acc[mi][ni][0], acc[mi][ni][1]};
            float2 v1 = {acc[mi][ni][2], acc[mi][ni][3]};
            *(float2*)&ctx[((size_t)(b * SEQ + q0)) * D_MODEL + h * DK + col] = v0;
            *(float2*)&ctx[((size_t)(b * SEQ + q0 + 8)) * D_MODEL + h * DK + col] = v1;
        }
    }
}

// ---------------------------------------------------------------------------
extern "C" void kernel_launch(void* const* d_in, const int* in_sizes, int n_in,
                              void* d_out, int out_size)
{
    const float* query = (const float*)d_in[0];
    const float* key   = (const float*)d_in[1];
    const float* value = (const float*)d_in[2];
    const float* Wq = (const float*)d_in[3];
    const float* bq = (const float*)d_in[4];
    const float* Wk = (const float*)d_in[5];
    const float* bk = (const float*)d_in[6];
    const float* Wv = (const float*)d_in[7];
    const float* bv = (const float*)d_in[8];
    const float* Wo = (const float*)d_in[9];
    const float* bo = (const float*)d_in[10];

    float* out  = (float*)d_out;
    float* attn = (float*)d_out + OUT_ELEMS;

    float* Qp; cudaGetSymbolAddress((void**)&Qp, g_Q);
    float* Kp; cudaGetSymbolAddress((void**)&Kp, g_K);
    float* Vp; cudaGetSymbolAddress((void**)&Vp, g_V);
    float* Cp; cudaGetSymbolAddress((void**)&Cp, g_ctx);

    static int configured = 0;
    if (!configured) {
        cudaFuncSetAttribute(gemm_bias_tc, cudaFuncAttributeMaxDynamicSharedMemorySize,
                             PROJ_SMEM_BYTES);
        cudaFuncSetAttribute(scores_tc, cudaFuncAttributeMaxDynamicSharedMemorySize,
                             SC_SMEM_BYTES);
        cudaFuncSetAttribute(ctx_tc, cudaFuncAttributeMaxDynamicSharedMemorySize,
                             CTX_SMEM_BYTES);
        configured = 1;
    }

    dim3 gProj(D_MODEL / 128, MROWS / 128);   // (8, 32)
    dim3 gScores(SEQ / 128, NBH);             // (16, 32)
    dim3 gCtx(SEQ / 256, NBH);                // (8, 32)

    gemm_bias_tc<<<gProj, 256, PROJ_SMEM_BYTES>>>(query, Wq, bq, Qp);
    gemm_bias_tc<<<gProj, 256, PROJ_SMEM_BYTES>>>(key,   Wk, bk, Kp);
    gemm_bias_tc<<<gProj, 256, PROJ_SMEM_BYTES>>>(value, Wv, bv, Vp);

    scores_tc<<<gScores, 256, SC_SMEM_BYTES>>>(Qp, Kp, attn);
    ctx_tc<<<gCtx, 256, CTX_SMEM_BYTES>>>(attn, Vp, Cp);

    gemm_bias_tc<<<gProj, 256, PROJ_SMEM_BYTES>>>(Cp, Wo, bo, out);
}